// round 3
// baseline (speedup 1.0000x reference)
#include <cuda_runtime.h>
#include <cuda_bf16.h>
#include <cstdint>

#define NN 50000
#define CE 800000
#define C  128
#define NT 64               // node tile per GEMM block
#define GEMM_BLOCKS ((NN + NT - 1) / NT)   // 782
#define SMEM_BYTES (( (128*128)*2 + (128*NT)*2 ) * 4)   // 196608

// scratch (allocation-free rule: __device__ globals)
__device__ __align__(16) float g_h[(size_t)NN * C];
__device__ __align__(16) float g_agg[(size_t)NN * C];

// dtype flags resolved on-device (deterministic, capture-safe)
__device__ int g_ei_is64;    // 1: edge_index is int64, 0: int32
__device__ int g_mask_is4B;  // 1: masks are 4-byte (int32/float32), 0: 1-byte bool

// ---------------------------------------------------------------------------
// Sniff dtypes from buffer contents. All sampled reads are in-bounds under
// EITHER dtype hypothesis (we read far less than the minimum buffer size).
// ---------------------------------------------------------------------------
__global__ void sniff_kernel(const void* ei, const void* m0) {
    if (blockIdx.x != 0 || threadIdx.x != 0) return;

    // edge_index: if truly int64, every value is in [0, NN). If it's int32
    // data misread as int64, the high word is the NEXT index (rarely 0), so
    // values blow past NN almost surely across 256 samples.
    const long long* e64 = (const long long*)ei;
    int is64 = 1;
    for (int i = 0; i < 256; i++) {
        long long v = e64[i];
        if (v < 0 || v >= NN) { is64 = 0; break; }
    }
    g_ei_is64 = is64;

    // masks: 4-byte elements can only be 0, 1 (int32) or 0.0f/1.0f bits
    // (float32). Packed 1-byte bools misread as u32 give byte-pattern values
    // (0x0101..., 0x00010100, ...) outside that set.
    const unsigned* mu = (const unsigned*)m0;
    int is4B = 1;
    for (int i = 0; i < 256; i++) {
        unsigned v = mu[i];
        if (v != 0u && v != 1u && v != 0x3F800000u) { is4B = 0; break; }
    }
    g_mask_is4B = is4B;
}

// keep-mask loader: 4 consecutive channels starting at group index idx4
__device__ __forceinline__ uint4 load_mask4(const void* m, size_t idx4) {
    if (g_mask_is4B) {
        const uint4 v = ((const uint4*)m)[idx4];
        return make_uint4(v.x, v.y, v.z, v.w);
    }
    const uchar4 v = ((const uchar4*)m)[idx4];
    return make_uint4(v.x, v.y, v.z, v.w);
}

// ---------------------------------------------------------------------------
// K0: h = dropout(x) (scale 2.5 on keep), agg = 0
// ---------------------------------------------------------------------------
__global__ void init_kernel(const float* __restrict__ x, const void* __restrict__ d0) {
    size_t i = (size_t)blockIdx.x * blockDim.x + threadIdx.x;   // float4 index
    if (i >= (size_t)NN * (C / 4)) return;
    float4 v = reinterpret_cast<const float4*>(x)[i];
    uint4 m = load_mask4(d0, i);
    float4 r;
    r.x = m.x ? v.x * 2.5f : 0.0f;
    r.y = m.y ? v.y * 2.5f : 0.0f;
    r.z = m.z ? v.z * 2.5f : 0.0f;
    r.w = m.w ? v.w * 2.5f : 0.0f;
    reinterpret_cast<float4*>(g_h)[i] = r;
    reinterpret_cast<float4*>(g_agg)[i] = make_float4(0.f, 0.f, 0.f, 0.f);
}

// ---------------------------------------------------------------------------
// Scatter: agg[dst] += h[src]. One warp per edge, one float4 per lane,
// vector reduction (1 L2 message / 16B).
// ---------------------------------------------------------------------------
__global__ void scatter_kernel(const void* __restrict__ ei) {
    unsigned gid = blockIdx.x * blockDim.x + threadIdx.x;
    unsigned e = gid >> 5;
    if (e >= CE) return;
    unsigned lane = gid & 31;
    unsigned s, d;
    if (g_ei_is64) {
        s = (unsigned)((const long long*)ei)[e];
        d = (unsigned)((const long long*)ei)[CE + e];
    } else {
        s = (unsigned)((const int*)ei)[e];
        d = (unsigned)((const int*)ei)[CE + e];
    }
    if (s >= NN || d >= NN) return;   // safety: degrade to rel_err, never IMA
    float4 v = reinterpret_cast<const float4*>(g_h + (size_t)s * C)[lane];
    float* dst = g_agg + (size_t)d * C + lane * 4;
    asm volatile("red.global.add.v4.f32 [%0], {%1, %2, %3, %4};"
                 :: "l"(dst), "f"(v.x), "f"(v.y), "f"(v.z), "f"(v.w)
                 : "memory");
}

// ---------------------------------------------------------------------------
// GEMM: out[n][o] = sum_k agg[n][k]*Wrel[o][k] + h[n][k]*Wroot[o][k] + b[o]
// Mid layers: relu -> dropout -> write back to g_h, zero own agg tile.
// Final layer: write to d_out.
//
// smem layout (all K-major so compute loads are coalesced/broadcast):
//   sWr[k][o]  128x128     sWo[k][o]  128x128
//   sA [k][n]  128x64      sH [k][n]  128x64
// Thread (og = tid&31 -> 4 outputs, ng = tid>>5 -> 8 nodes): 8x4 accumulators.
// ---------------------------------------------------------------------------
template <bool FINAL>
__global__ void __launch_bounds__(256, 1)
gemm_kernel(const float* __restrict__ Wrel, const float* __restrict__ Wroot,
            const float* __restrict__ b, const void* __restrict__ drop,
            float* __restrict__ out) {
    extern __shared__ float sm[];
    float* sWr = sm;                  // 16384 floats
    float* sWo = sm + 16384;          // 16384
    float* sA  = sm + 32768;          // 8192
    float* sH  = sm + 40960;          // 8192

    const int tid = threadIdx.x;
    const int tile0 = blockIdx.x * NT;

    // --- load weights transposed into smem
    for (int i = tid; i < 4096; i += 256) {      // 4096 float4 per matrix
        int o = i & 127, kq = i >> 7;            // kq = k/4
        float4 r = reinterpret_cast<const float4*>(Wrel)[o * 32 + kq];
        float4 t = reinterpret_cast<const float4*>(Wroot)[o * 32 + kq];
        int kb = kq * 4;
        sWr[(kb + 0) * 128 + o] = r.x;
        sWr[(kb + 1) * 128 + o] = r.y;
        sWr[(kb + 2) * 128 + o] = r.z;
        sWr[(kb + 3) * 128 + o] = r.w;
        sWo[(kb + 0) * 128 + o] = t.x;
        sWo[(kb + 1) * 128 + o] = t.y;
        sWo[(kb + 2) * 128 + o] = t.z;
        sWo[(kb + 3) * 128 + o] = t.w;
    }

    // --- load agg / h tiles transposed
    for (int i = tid; i < 2048; i += 256) {      // 2048 float4 per array
        int n = i & 63, kq = i >> 6;
        int gn = tile0 + n;
        float4 va = make_float4(0.f, 0.f, 0.f, 0.f);
        float4 vh = va;
        if (gn < NN) {
            va = reinterpret_cast<const float4*>(g_agg)[(size_t)gn * 32 + kq];
            vh = reinterpret_cast<const float4*>(g_h)[(size_t)gn * 32 + kq];
        }
        int kb = kq * 4;
        sA[(kb + 0) * 64 + n] = va.x;
        sA[(kb + 1) * 64 + n] = va.y;
        sA[(kb + 2) * 64 + n] = va.z;
        sA[(kb + 3) * 64 + n] = va.w;
        sH[(kb + 0) * 64 + n] = vh.x;
        sH[(kb + 1) * 64 + n] = vh.y;
        sH[(kb + 2) * 64 + n] = vh.z;
        sH[(kb + 3) * 64 + n] = vh.w;
    }
    __syncthreads();

    const int og = tid & 31;     // outputs [og*4, og*4+4)
    const int ng = tid >> 5;     // nodes   [ng*8, ng*8+8) within tile

    float acc[8][4];
    #pragma unroll
    for (int nn = 0; nn < 8; nn++)
        #pragma unroll
        for (int oo = 0; oo < 4; oo++) acc[nn][oo] = 0.0f;

    const float* pWr = sWr + og * 4;
    const float* pWo = sWo + og * 4;
    const float* pA  = sA + ng * 8;
    const float* pH  = sH + ng * 8;

    #pragma unroll 4
    for (int k = 0; k < 128; ++k) {
        const float4 wr = *reinterpret_cast<const float4*>(pWr + k * 128);
        const float4 wo = *reinterpret_cast<const float4*>(pWo + k * 128);
        const float4 a0 = *reinterpret_cast<const float4*>(pA + k * 64);
        const float4 a1 = *reinterpret_cast<const float4*>(pA + k * 64 + 4);
        const float4 h0 = *reinterpret_cast<const float4*>(pH + k * 64);
        const float4 h1 = *reinterpret_cast<const float4*>(pH + k * 64 + 4);
        float av[8] = {a0.x, a0.y, a0.z, a0.w, a1.x, a1.y, a1.z, a1.w};
        float hv[8] = {h0.x, h0.y, h0.z, h0.w, h1.x, h1.y, h1.z, h1.w};
        float wrv[4] = {wr.x, wr.y, wr.z, wr.w};
        float wov[4] = {wo.x, wo.y, wo.z, wo.w};
        #pragma unroll
        for (int nn = 0; nn < 8; nn++)
            #pragma unroll
            for (int oo = 0; oo < 4; oo++)
                acc[nn][oo] += av[nn] * wrv[oo] + hv[nn] * wov[oo];
    }

    // --- epilogue
    const float4 bv = *reinterpret_cast<const float4*>(b + og * 4);
    #pragma unroll
    for (int nn = 0; nn < 8; nn++) {
        int n = tile0 + ng * 8 + nn;
        if (n >= NN) break;
        float4 v;
        v.x = acc[nn][0] + bv.x;
        v.y = acc[nn][1] + bv.y;
        v.z = acc[nn][2] + bv.z;
        v.w = acc[nn][3] + bv.w;
        if (!FINAL) {
            v.x = fmaxf(v.x, 0.0f);
            v.y = fmaxf(v.y, 0.0f);
            v.z = fmaxf(v.z, 0.0f);
            v.w = fmaxf(v.w, 0.0f);
            uint4 m = load_mask4(drop, (size_t)n * 32 + og);
            v.x = m.x ? v.x * 2.5f : 0.0f;
            v.y = m.y ? v.y * 2.5f : 0.0f;
            v.z = m.z ? v.z * 2.5f : 0.0f;
            v.w = m.w ? v.w * 2.5f : 0.0f;
            reinterpret_cast<float4*>(g_h)[(size_t)n * 32 + og] = v;
        } else {
            reinterpret_cast<float4*>(out)[(size_t)n * 32 + og] = v;
        }
    }

    if (!FINAL) {
        // zero this block's agg tile for the next layer's scatter
        const float4 z = make_float4(0.f, 0.f, 0.f, 0.f);
        for (int i = tid; i < NT * 32; i += 256) {
            int n = tile0 + (i >> 5);
            if (n < NN)
                reinterpret_cast<float4*>(g_agg)[(size_t)n * 32 + (i & 31)] = z;
        }
    }
}

// ---------------------------------------------------------------------------
extern "C" void kernel_launch(void* const* d_in, const int* in_sizes, int n_in,
                              void* d_out, int out_size) {
    const float* x   = (const float*)d_in[0];
    const void*  ei  = d_in[1];
    const float* Wr0 = (const float*)d_in[2];
    const float* Wo0 = (const float*)d_in[3];
    const float* b0  = (const float*)d_in[4];
    const float* Wr1 = (const float*)d_in[5];
    const float* Wo1 = (const float*)d_in[6];
    const float* b1  = (const float*)d_in[7];
    const float* Wr2 = (const float*)d_in[8];
    const float* Wo2 = (const float*)d_in[9];
    const float* b2  = (const float*)d_in[10];
    const void*  dr0 = d_in[11];
    const void*  dr1 = d_in[12];
    const void*  dr2 = d_in[13];
    float* out = (float*)d_out;

    cudaFuncSetAttribute(gemm_kernel<false>,
                         cudaFuncAttributeMaxDynamicSharedMemorySize, SMEM_BYTES);
    cudaFuncSetAttribute(gemm_kernel<true>,
                         cudaFuncAttributeMaxDynamicSharedMemorySize, SMEM_BYTES);

    const int initBlocks = (NN * (C / 4) + 255) / 256;           // 6250
    const int scatBlocks = ((CE * 32) + 255) / 256;              // 100000

    sniff_kernel<<<1, 32>>>(ei, dr0);
    init_kernel<<<initBlocks, 256>>>(x, dr0);

    scatter_kernel<<<scatBlocks, 256>>>(ei);
    gemm_kernel<false><<<GEMM_BLOCKS, 256, SMEM_BYTES>>>(Wr0, Wo0, b0, dr1, nullptr);

    scatter_kernel<<<scatBlocks, 256>>>(ei);
    gemm_kernel<false><<<GEMM_BLOCKS, 256, SMEM_BYTES>>>(Wr1, Wo1, b1, dr2, nullptr);

    scatter_kernel<<<scatBlocks, 256>>>(ei);
    gemm_kernel<true><<<GEMM_BLOCKS, 256, SMEM_BYTES>>>(Wr2, Wo2, b2, nullptr, out);
}

// round 5
// speedup vs baseline: 1.4986x; 1.4986x over previous
#include <cuda_runtime.h>
#include <cuda_bf16.h>
#include <cstdint>

#define NN 50000
#define CE 800000
#define C  128
#define NT 64                    // nodes per GEMM tile
#define NTILES ((NN + NT - 1) / NT)        // 782
#define GRID_P 152               // persistent CTAs (GB300: 152 SMs)

#define KK 256                   // combined K (agg 0..127, h 128..255)
#define STRIDE 264               // floats per smem row (264 % 32 == 8)
#define SW_FLOATS (128 * STRIDE) // 33792
#define SX_FLOATS (NT * STRIDE)  // 16896
#define SMEM_BYTES ((SW_FLOATS + SX_FLOATS) * 4)   // 202752

// scratch (allocation-free rule: __device__ globals)
__device__ __align__(16) float g_h[(size_t)NN * C];
__device__ __align__(16) float g_agg[(size_t)NN * C];

// dtype flags resolved on-device (deterministic, capture-safe)
__device__ int g_ei_is64;    // 1: edge_index is int64, 0: int32
__device__ int g_mask_is4B;  // 1: masks are 4-byte, 0: 1-byte bool

// ---------------------------------------------------------------------------
__global__ void sniff_kernel(const void* ei, const void* m0) {
    if (blockIdx.x != 0 || threadIdx.x != 0) return;
    const long long* e64 = (const long long*)ei;
    int is64 = 1;
    for (int i = 0; i < 256; i++) {
        long long v = e64[i];
        if (v < 0 || v >= NN) { is64 = 0; break; }
    }
    g_ei_is64 = is64;
    const unsigned* mu = (const unsigned*)m0;
    int is4B = 1;
    for (int i = 0; i < 256; i++) {
        unsigned v = mu[i];
        if (v != 0u && v != 1u && v != 0x3F800000u) { is4B = 0; break; }
    }
    g_mask_is4B = is4B;
}

__device__ __forceinline__ uint4 load_mask4(const void* m, size_t idx4, int m4B) {
    if (m4B) {
        const uint4 v = ((const uint4*)m)[idx4];
        return make_uint4(v.x, v.y, v.z, v.w);
    }
    const uchar4 v = ((const uchar4*)m)[idx4];
    return make_uint4(v.x, v.y, v.z, v.w);
}

__device__ __forceinline__ uint2 load_mask2(const void* m, size_t off, int m4B) {
    if (m4B) {
        const uint2 v = *(const uint2*)((const unsigned*)m + off);
        return v;
    }
    const unsigned char* p = (const unsigned char*)m + off;
    return make_uint2(p[0], p[1]);
}

__device__ __forceinline__ uint32_t f2tf32(float f) {
    uint32_t r;
    asm("cvt.rna.tf32.f32 %0, %1;" : "=r"(r) : "f"(f));
    return r;
}

// ---------------------------------------------------------------------------
// K0: h = dropout(x) (scale 2.5 on keep), agg = 0
// ---------------------------------------------------------------------------
__global__ void init_kernel(const float* __restrict__ x, const void* __restrict__ d0) {
    const int m4B = g_mask_is4B;
    size_t i = (size_t)blockIdx.x * blockDim.x + threadIdx.x;
    if (i >= (size_t)NN * (C / 4)) return;
    float4 v = reinterpret_cast<const float4*>(x)[i];
    uint4 m = load_mask4(d0, i, m4B);
    float4 r;
    r.x = m.x ? v.x * 2.5f : 0.0f;
    r.y = m.y ? v.y * 2.5f : 0.0f;
    r.z = m.z ? v.z * 2.5f : 0.0f;
    r.w = m.w ? v.w * 2.5f : 0.0f;
    reinterpret_cast<float4*>(g_h)[i] = r;
    reinterpret_cast<float4*>(g_agg)[i] = make_float4(0.f, 0.f, 0.f, 0.f);
}

// ---------------------------------------------------------------------------
// Scatter: agg[dst] += h[src]. One warp per edge, vector L2 reduction.
// ---------------------------------------------------------------------------
__global__ void scatter_kernel(const void* __restrict__ ei) {
    unsigned gid = blockIdx.x * blockDim.x + threadIdx.x;
    unsigned e = gid >> 5;
    if (e >= CE) return;
    unsigned lane = gid & 31;
    unsigned s, d;
    if (g_ei_is64) {
        s = (unsigned)((const long long*)ei)[e];
        d = (unsigned)((const long long*)ei)[CE + e];
    } else {
        s = (unsigned)((const int*)ei)[e];
        d = (unsigned)((const int*)ei)[CE + e];
    }
    if (s >= NN || d >= NN) return;
    float4 v = reinterpret_cast<const float4*>(g_h + (size_t)s * C)[lane];
    float* dst = g_agg + (size_t)d * C + lane * 4;
    asm volatile("red.global.add.v4.f32 [%0], {%1, %2, %3, %4};"
                 :: "l"(dst), "f"(v.x), "f"(v.y), "f"(v.z), "f"(v.w)
                 : "memory");
}

// ---------------------------------------------------------------------------
// Persistent tf32 tensor-core GEMM.
//   out[n][o] = sum_{k<256} X[n][k] * W[o][k] + b[o]
//   X = [agg | h], W = [Wrel | Wroot]  (combined K)
// smem: sW[128 out][STRIDE] (tf32, K-permuted), sX[64 node][STRIDE].
// Permutation within each 8-K group: pos(k) = (k&3)*2 + ((k&7)>>2), so the
// mma fragment pair (k=c, k=c+4) is contiguous -> LDS.64 loads.
// Warp tile 32x32 (m16n8k8 mma), CTA tile 64 nodes x 128 outs, 8 warps (2x4).
// ---------------------------------------------------------------------------
template <bool FINAL>
__global__ void __launch_bounds__(256, 1)
gemm_kernel(const float* __restrict__ Wrel, const float* __restrict__ Wroot,
            const float* __restrict__ b, const void* __restrict__ drop,
            float* __restrict__ out) {
    extern __shared__ float sm[];
    float* sW = sm;
    float* sX = sm + SW_FLOATS;

    const int tid = threadIdx.x;
    const int m4B = g_mask_is4B;

    // ---- stage combined weights once (tf32, permuted) ----
    for (int i = tid; i < 128 * 64; i += 256) {     // 128 outs x 64 combined-kq
        int o = i >> 6, kqc = i & 63;
        float4 v;
        int kbase;
        if (kqc < 32) { v = reinterpret_cast<const float4*>(Wrel)[o * 32 + kqc];  kbase = kqc * 4; }
        else          { v = reinterpret_cast<const float4*>(Wroot)[o * 32 + (kqc - 32)]; kbase = 128 + (kqc - 32) * 4; }
        int g = kbase >> 3, p = (kbase >> 2) & 1;
        float* dst = sW + o * STRIDE + g * 8 + p;
        dst[0] = __uint_as_float(f2tf32(v.x));
        dst[2] = __uint_as_float(f2tf32(v.y));
        dst[4] = __uint_as_float(f2tf32(v.z));
        dst[6] = __uint_as_float(f2tf32(v.w));
    }

    const int wid = tid >> 5, lane = tid & 31;
    const int warpM = wid & 1, warpN = wid >> 1;
    const int lr = lane >> 2;        // 0..7
    const int lc = lane & 3;         // 0..3

    // per-thread bias (fixed per kernel)
    float2 bias[4];
    #pragma unroll
    for (int nf = 0; nf < 4; nf++) {
        int o = warpN * 32 + nf * 8 + lc * 2;
        bias[nf] = *(const float2*)(b + o);
    }

    for (int tile = blockIdx.x; tile < NTILES; tile += GRID_P) {
        const int tile0 = tile * NT;
        __syncthreads();   // previous compute done before sX overwrite

        // ---- stage X tile (tf32, permuted) ----
        for (int i = tid; i < NT * 64; i += 256) {   // 64 nodes x 64 combined-kq
            int n = i >> 6, kqc = i & 63;
            int node = tile0 + n;
            float4 v = make_float4(0.f, 0.f, 0.f, 0.f);
            if (node < NN) {
                if (kqc < 32) v = reinterpret_cast<const float4*>(g_agg)[(size_t)node * 32 + kqc];
                else          v = reinterpret_cast<const float4*>(g_h)[(size_t)node * 32 + (kqc - 32)];
            }
            int kbase = (kqc < 32) ? kqc * 4 : 128 + (kqc - 32) * 4;
            int g = kbase >> 3, p = (kbase >> 2) & 1;
            float* dst = sX + n * STRIDE + g * 8 + p;
            dst[0] = __uint_as_float(f2tf32(v.x));
            dst[2] = __uint_as_float(f2tf32(v.y));
            dst[4] = __uint_as_float(f2tf32(v.z));
            dst[6] = __uint_as_float(f2tf32(v.w));
        }
        __syncthreads();

        // ---- mma mainloop: 32 k8-steps ----
        float d[2][4][4];
        #pragma unroll
        for (int mf = 0; mf < 2; mf++)
            #pragma unroll
            for (int nf = 0; nf < 4; nf++)
                #pragma unroll
                for (int j = 0; j < 4; j++) d[mf][nf][j] = 0.0f;

        #pragma unroll 2
        for (int ks = 0; ks < 32; ks++) {
            const int kb = ks * 8 + lc * 2;
            uint32_t a[2][4];
            #pragma unroll
            for (int mf = 0; mf < 2; mf++) {
                int row0 = warpM * 32 + mf * 16 + lr;
                float2 v0 = *(const float2*)(sX + row0 * STRIDE + kb);
                float2 v1 = *(const float2*)(sX + (row0 + 8) * STRIDE + kb);
                a[mf][0] = __float_as_uint(v0.x);
                a[mf][2] = __float_as_uint(v0.y);
                a[mf][1] = __float_as_uint(v1.x);
                a[mf][3] = __float_as_uint(v1.y);
            }
            uint32_t bb[4][2];
            #pragma unroll
            for (int nf = 0; nf < 4; nf++) {
                int orow = warpN * 32 + nf * 8 + lr;
                float2 w = *(const float2*)(sW + orow * STRIDE + kb);
                bb[nf][0] = __float_as_uint(w.x);
                bb[nf][1] = __float_as_uint(w.y);
            }
            #pragma unroll
            for (int mf = 0; mf < 2; mf++)
                #pragma unroll
                for (int nf = 0; nf < 4; nf++) {
                    asm volatile(
                        "mma.sync.aligned.m16n8k8.row.col.f32.tf32.tf32.f32 "
                        "{%0,%1,%2,%3}, {%4,%5,%6,%7}, {%8,%9}, {%0,%1,%2,%3};"
                        : "+f"(d[mf][nf][0]), "+f"(d[mf][nf][1]),
                          "+f"(d[mf][nf][2]), "+f"(d[mf][nf][3])
                        : "r"(a[mf][0]), "r"(a[mf][1]), "r"(a[mf][2]), "r"(a[mf][3]),
                          "r"(bb[nf][0]), "r"(bb[nf][1]));
                }
        }

        // ---- epilogue: bias (+relu+dropout for non-final), store ----
        #pragma unroll
        for (int mf = 0; mf < 2; mf++) {
            #pragma unroll
            for (int rr = 0; rr < 2; rr++) {
                int node = tile0 + warpM * 32 + mf * 16 + rr * 8 + lr;
                if (node >= NN) continue;
                #pragma unroll
                for (int nf = 0; nf < 4; nf++) {
                    int o = warpN * 32 + nf * 8 + lc * 2;
                    float vx = d[mf][nf][rr * 2 + 0] + bias[nf].x;
                    float vy = d[mf][nf][rr * 2 + 1] + bias[nf].y;
                    if (!FINAL) {
                        vx = fmaxf(vx, 0.0f);
                        vy = fmaxf(vy, 0.0f);
                        uint2 m = load_mask2(drop, (size_t)node * C + o, m4B);
                        vx = m.x ? vx * 2.5f : 0.0f;
                        vy = m.y ? vy * 2.5f : 0.0f;
                        *(float2*)(g_h + (size_t)node * C + o) = make_float2(vx, vy);
                    } else {
                        *(float2*)(out + (size_t)node * C + o) = make_float2(vx, vy);
                    }
                }
            }
        }

        if (!FINAL) {
            // zero this tile's agg rows for the next layer's scatter
            const float4 z = make_float4(0.f, 0.f, 0.f, 0.f);
            for (int i = tid; i < NT * 32; i += 256) {
                int n = tile0 + (i >> 5);
                if (n < NN)
                    reinterpret_cast<float4*>(g_agg)[(size_t)n * 32 + (i & 31)] = z;
            }
        }
    }
}

// ---------------------------------------------------------------------------
extern "C" void kernel_launch(void* const* d_in, const int* in_sizes, int n_in,
                              void* d_out, int out_size) {
    const float* x   = (const float*)d_in[0];
    const void*  ei  = d_in[1];
    const float* Wr0 = (const float*)d_in[2];
    const float* Wo0 = (const float*)d_in[3];
    const float* b0  = (const float*)d_in[4];
    const float* Wr1 = (const float*)d_in[5];
    const float* Wo1 = (const float*)d_in[6];
    const float* b1  = (const float*)d_in[7];
    const float* Wr2 = (const float*)d_in[8];
    const float* Wo2 = (const float*)d_in[9];
    const float* b2  = (const float*)d_in[10];
    const void*  dr0 = d_in[11];
    const void*  dr1 = d_in[12];
    const void*  dr2 = d_in[13];
    float* out = (float*)d_out;

    cudaFuncSetAttribute(gemm_kernel<false>,
                         cudaFuncAttributeMaxDynamicSharedMemorySize, SMEM_BYTES);
    cudaFuncSetAttribute(gemm_kernel<true>,
                         cudaFuncAttributeMaxDynamicSharedMemorySize, SMEM_BYTES);

    const int initBlocks = (NN * (C / 4) + 255) / 256;
    const int scatBlocks = ((CE * 32) + 255) / 256;

    sniff_kernel<<<1, 32>>>(ei, dr0);
    init_kernel<<<initBlocks, 256>>>(x, dr0);

    scatter_kernel<<<scatBlocks, 256>>>(ei);
    gemm_kernel<false><<<GRID_P, 256, SMEM_BYTES>>>(Wr0, Wo0, b0, dr1, nullptr);

    scatter_kernel<<<scatBlocks, 256>>>(ei);
    gemm_kernel<false><<<GRID_P, 256, SMEM_BYTES>>>(Wr1, Wo1, b1, dr2, nullptr);

    scatter_kernel<<<scatBlocks, 256>>>(ei);
    gemm_kernel<true><<<GRID_P, 256, SMEM_BYTES>>>(Wr2, Wo2, b2, nullptr, out);
}

// round 7
// speedup vs baseline: 1.5734x; 1.0500x over previous
#include <cuda_runtime.h>
#include <cstdint>

#define NN 50000
#define CE 800000
#define C  128
#define NT 64
#define NTILES 782               // ceil(50000/64)
#define GRID_G 304               // 2 CTAs per SM * 152 SMs
#define S 132                    // smem row stride (floats), 132%32=4
#define SW_FL (128*S)            // 16896 floats
#define SX_FL (NT*S)             // 8448 floats
#define SMEM_B ((SW_FL+SX_FL)*4) // 101376 bytes -> 2 CTAs/SM

// scratch (allocation-free rule: __device__ globals)
__device__ __align__(16) float g_h[(size_t)NN * C];
__device__ __align__(16) float g_agg[(size_t)NN * C];
__device__ __align__(16) float g_y[(size_t)NN * C];

// dtype flags resolved on-device
__device__ int g_ei_is64;
__device__ int g_mask_is4B;

// ---------------------------------------------------------------------------
__global__ void sniff_kernel(const void* ei, const void* m0) {
    if (blockIdx.x != 0 || threadIdx.x != 0) return;
    const long long* e64 = (const long long*)ei;
    int is64 = 1;
    for (int i = 0; i < 256; i++) {
        long long v = e64[i];
        if (v < 0 || v >= NN) { is64 = 0; break; }
    }
    g_ei_is64 = is64;
    const unsigned* mu = (const unsigned*)m0;
    int is4B = 1;
    for (int i = 0; i < 256; i++) {
        unsigned v = mu[i];
        if (v != 0u && v != 1u && v != 0x3F800000u) { is4B = 0; break; }
    }
    g_mask_is4B = is4B;
}

__device__ __forceinline__ uint4 load_mask4(const void* m, size_t idx4, int m4B) {
    if (m4B) { const uint4 v = ((const uint4*)m)[idx4]; return make_uint4(v.x, v.y, v.z, v.w); }
    const uchar4 v = ((const uchar4*)m)[idx4];
    return make_uint4(v.x, v.y, v.z, v.w);
}
__device__ __forceinline__ uint2 load_mask2(const void* m, size_t off, int m4B) {
    if (m4B) return *(const uint2*)((const unsigned*)m + off);
    const unsigned char* p = (const unsigned char*)m + off;
    return make_uint2(p[0], p[1]);
}
__device__ __forceinline__ float tf32r(float f) {
    uint32_t r;
    asm("cvt.rna.tf32.f32 %0, %1;" : "=r"(r) : "f"(f));
    return __uint_as_float(r);
}
__device__ __forceinline__ uint32_t tf32u(float f) {
    uint32_t r;
    asm("cvt.rna.tf32.f32 %0, %1;" : "=r"(r) : "f"(f));
    return r;
}

// ---------------------------------------------------------------------------
// h = dropout(x) rounded to tf32, agg = 0
// ---------------------------------------------------------------------------
__global__ void init_kernel(const float* __restrict__ x, const void* __restrict__ d0) {
    const int m4B = g_mask_is4B;
    size_t i = (size_t)blockIdx.x * blockDim.x + threadIdx.x;
    if (i >= (size_t)NN * (C / 4)) return;
    float4 v = reinterpret_cast<const float4*>(x)[i];
    uint4 m = load_mask4(d0, i, m4B);
    float4 r;
    r.x = m.x ? tf32r(v.x * 2.5f) : 0.0f;
    r.y = m.y ? tf32r(v.y * 2.5f) : 0.0f;
    r.z = m.z ? tf32r(v.z * 2.5f) : 0.0f;
    r.w = m.w ? tf32r(v.w * 2.5f) : 0.0f;
    reinterpret_cast<float4*>(g_h)[i] = r;
    reinterpret_cast<float4*>(g_agg)[i] = make_float4(0.f, 0.f, 0.f, 0.f);
}

// ---------------------------------------------------------------------------
// Scatter: agg[dst] += h[src], warp per edge, vector L2 reduction
// ---------------------------------------------------------------------------
__global__ void scatter_kernel(const void* __restrict__ ei) {
    unsigned gid = blockIdx.x * blockDim.x + threadIdx.x;
    unsigned e = gid >> 5;
    if (e >= CE) return;
    unsigned lane = gid & 31;
    unsigned s, d;
    if (g_ei_is64) {
        s = (unsigned)((const long long*)ei)[e];
        d = (unsigned)((const long long*)ei)[CE + e];
    } else {
        s = (unsigned)((const int*)ei)[e];
        d = (unsigned)((const int*)ei)[CE + e];
    }
    if (s >= NN || d >= NN) return;
    float4 v = reinterpret_cast<const float4*>(g_h + (size_t)s * C)[lane];
    float* dst = g_agg + (size_t)d * C + lane * 4;
    asm volatile("red.global.add.v4.f32 [%0], {%1, %2, %3, %4};"
                 :: "l"(dst), "f"(v.x), "f"(v.y), "f"(v.z), "f"(v.w)
                 : "memory");
}

// ---------------------------------------------------------------------------
// Half-K GEMM (K=128), tf32 mma.sync, persistent, cp.async-pipelined.
// MODE 0 (root):    g_y[n][o]  = X(h)·W^T + bias
// MODE 1 (combine): g_h[n][o]  = tf32(drop(relu(X(agg)·W^T + Y)));  agg tile = 0
// MODE 2 (final):   out[n][o]  = X(agg)·W^T + Y
// smem: sW[128][S] (tf32-rounded at stage), sX[64][S] raw fp32 (cp.async).
// A-fragments get cvt.rna.tf32 in-register before mma (truncation bias was
// the R5 accuracy bug; h-sourced tiles are pre-rounded so that cvt is exact).
// ---------------------------------------------------------------------------
template <int MODE>
__global__ void __launch_bounds__(256, 2)
gemm_half(const float* __restrict__ W, const float* __restrict__ bias,
          const void* __restrict__ drop, const float* __restrict__ Xsrc,
          float* __restrict__ outp) {
    extern __shared__ float sm[];
    float* sW = sm;
    float* sX = sm + SW_FL;

    const int tid = threadIdx.x;
    const int m4B = g_mask_is4B;

    // stage W once per CTA (cvt.rna to tf32), STS.128 conflict-free
    #pragma unroll 4
    for (int j = tid; j < 128 * 32; j += 256) {
        int o = j >> 5, kq = j & 31;
        float4 v = ((const float4*)W)[j];
        float4 t = make_float4(tf32r(v.x), tf32r(v.y), tf32r(v.z), tf32r(v.w));
        *(float4*)(sW + o * S + kq * 4) = t;
    }

    uint32_t sXaddr;
    asm("{.reg .u64 t; cvta.to.shared.u64 t, %1; cvt.u32.u64 %0, t;}"
        : "=r"(sXaddr) : "l"(sX));

    const int wid = tid >> 5, lane = tid & 31;
    const int warpM = wid & 1, warpN = wid >> 1;
    const int lr = lane >> 2, lc = lane & 3;

    float2 bias2[4];
    if (MODE == 0) {
        #pragma unroll
        for (int nf = 0; nf < 4; nf++)
            bias2[nf] = *(const float2*)(bias + warpN * 32 + nf * 8 + lc * 2);
    }

    // prefetch first tile (8 x 16B cp.async per thread)
    int tile = blockIdx.x;
    {
        #pragma unroll
        for (int j = 0; j < 8; j++) {
            int idx = tid + j * 256;
            int row = idx & 63, ch = idx >> 6;
            int node = tile * NT + row;
            const float* src = Xsrc + (size_t)(node < NN ? node : 0) * C + ch * 4;
            int sz = (node < NN) ? 16 : 0;
            asm volatile("cp.async.cg.shared.global [%0], [%1], 16, %2;"
                         :: "r"(sXaddr + (unsigned)(row * S + ch * 4) * 4), "l"(src), "r"(sz));
        }
        asm volatile("cp.async.commit_group;" ::: "memory");
    }

    for (; tile < NTILES; tile += GRID_G) {
        asm volatile("cp.async.wait_group 0;" ::: "memory");
        __syncthreads();

        float d[2][4][4];
        #pragma unroll
        for (int mf = 0; mf < 2; mf++)
            #pragma unroll
            for (int nf = 0; nf < 4; nf++)
                #pragma unroll
                for (int j = 0; j < 4; j++) d[mf][nf][j] = 0.0f;

        #pragma unroll 8
        for (int ks = 0; ks < 16; ks++) {
            const int kb = ks * 8;
            uint32_t a[2][4], bb[4][2];
            #pragma unroll
            for (int mf = 0; mf < 2; mf++) {
                const float* p = sX + (warpM * 32 + mf * 16 + lr) * S + kb + lc;
                a[mf][0] = tf32u(p[0]);
                a[mf][2] = tf32u(p[4]);
                a[mf][1] = tf32u(p[8 * S]);
                a[mf][3] = tf32u(p[8 * S + 4]);
            }
            #pragma unroll
            for (int nf = 0; nf < 4; nf++) {
                const float* p = sW + (warpN * 32 + nf * 8 + lr) * S + kb + lc;
                bb[nf][0] = __float_as_uint(p[0]);
                bb[nf][1] = __float_as_uint(p[4]);
            }
            #pragma unroll
            for (int mf = 0; mf < 2; mf++)
                #pragma unroll
                for (int nf = 0; nf < 4; nf++) {
                    asm volatile(
                        "mma.sync.aligned.m16n8k8.row.col.f32.tf32.tf32.f32 "
                        "{%0,%1,%2,%3}, {%4,%5,%6,%7}, {%8,%9}, {%0,%1,%2,%3};"
                        : "+f"(d[mf][nf][0]), "+f"(d[mf][nf][1]),
                          "+f"(d[mf][nf][2]), "+f"(d[mf][nf][3])
                        : "r"(a[mf][0]), "r"(a[mf][1]), "r"(a[mf][2]), "r"(a[mf][3]),
                          "r"(bb[nf][0]), "r"(bb[nf][1]));
                }
        }
        __syncthreads();

        // issue next tile's copies, then do the epilogue under them
        int nxt = tile + GRID_G;
        if (nxt < NTILES) {
            #pragma unroll
            for (int j = 0; j < 8; j++) {
                int idx = tid + j * 256;
                int row = idx & 63, ch = idx >> 6;
                int node = nxt * NT + row;
                const float* src = Xsrc + (size_t)(node < NN ? node : 0) * C + ch * 4;
                int sz = (node < NN) ? 16 : 0;
                asm volatile("cp.async.cg.shared.global [%0], [%1], 16, %2;"
                             :: "r"(sXaddr + (unsigned)(row * S + ch * 4) * 4), "l"(src), "r"(sz));
            }
        }
        asm volatile("cp.async.commit_group;" ::: "memory");

        // ---- epilogue ----
        #pragma unroll
        for (int mf = 0; mf < 2; mf++) {
            #pragma unroll
            for (int rr = 0; rr < 2; rr++) {
                int node = tile * NT + warpM * 32 + mf * 16 + rr * 8 + lr;
                if (node >= NN) continue;
                #pragma unroll
                for (int nf = 0; nf < 4; nf++) {
                    int o = warpN * 32 + nf * 8 + lc * 2;
                    float vx = d[mf][nf][rr * 2 + 0];
                    float vy = d[mf][nf][rr * 2 + 1];
                    size_t off = (size_t)node * C + o;
                    if (MODE == 0) {
                        vx += bias2[nf].x; vy += bias2[nf].y;
                        *(float2*)(g_y + off) = make_float2(vx, vy);
                    } else {
                        float2 y = *(const float2*)(g_y + off);
                        vx += y.x; vy += y.y;
                        if (MODE == 1) {
                            vx = fmaxf(vx, 0.0f);
                            vy = fmaxf(vy, 0.0f);
                            uint2 m = load_mask2(drop, off, m4B);
                            vx = m.x ? tf32r(vx * 2.5f) : 0.0f;
                            vy = m.y ? tf32r(vy * 2.5f) : 0.0f;
                            *(float2*)(g_h + off) = make_float2(vx, vy);
                        } else {
                            *(float2*)(outp + off) = make_float2(vx, vy);
                        }
                    }
                }
            }
        }
        if (MODE == 1) {
            const float4 z = make_float4(0.f, 0.f, 0.f, 0.f);
            for (int i = tid; i < NT * 32; i += 256) {
                int n = tile * NT + (i >> 5);
                if (n < NN)
                    reinterpret_cast<float4*>(g_agg)[(size_t)n * 32 + (i & 31)] = z;
            }
        }
    }
}

// ---------------------------------------------------------------------------
extern "C" void kernel_launch(void* const* d_in, const int* in_sizes, int n_in,
                              void* d_out, int out_size) {
    const float* x   = (const float*)d_in[0];
    const void*  ei  = d_in[1];
    const float* Wr[3] = {(const float*)d_in[2], (const float*)d_in[5], (const float*)d_in[8]};
    const float* Wo[3] = {(const float*)d_in[3], (const float*)d_in[6], (const float*)d_in[9]};
    const float* bv[3] = {(const float*)d_in[4], (const float*)d_in[7], (const float*)d_in[10]};
    const void*  dr[3] = {d_in[11], d_in[12], d_in[13]};
    float* out = (float*)d_out;

    static cudaStream_t s2 = nullptr;
    static cudaEvent_t evF = nullptr, evJ = nullptr;
    static float *p_h = nullptr, *p_agg = nullptr;
    if (!s2) {
        cudaStreamCreateWithFlags(&s2, cudaStreamNonBlocking);
        cudaEventCreateWithFlags(&evF, cudaEventDisableTiming);
        cudaEventCreateWithFlags(&evJ, cudaEventDisableTiming);
        cudaGetSymbolAddress((void**)&p_h, g_h);
        cudaGetSymbolAddress((void**)&p_agg, g_agg);
        cudaFuncSetAttribute(gemm_half<0>, cudaFuncAttributeMaxDynamicSharedMemorySize, SMEM_B);
        cudaFuncSetAttribute(gemm_half<1>, cudaFuncAttributeMaxDynamicSharedMemorySize, SMEM_B);
        cudaFuncSetAttribute(gemm_half<2>, cudaFuncAttributeMaxDynamicSharedMemorySize, SMEM_B);
    }

    const int initBlocks = (NN * (C / 4) + 255) / 256;
    const int scatBlocks = ((CE * 32) + 255) / 256;

    sniff_kernel<<<1, 32>>>(ei, dr[0]);
    init_kernel<<<initBlocks, 256>>>(x, dr[0]);

    for (int l = 0; l < 3; l++) {
        // fork: root pass (Y = h*Wroot^T + b) runs concurrently with scatter
        cudaEventRecord(evF, 0);
        cudaStreamWaitEvent(s2, evF, 0);
        gemm_half<0><<<GRID_G, 256, SMEM_B, s2>>>(Wo[l], bv[l], nullptr, p_h, nullptr);
        cudaEventRecord(evJ, s2);

        scatter_kernel<<<scatBlocks, 256>>>(ei);

        cudaStreamWaitEvent(0, evJ, 0);
        if (l < 2)
            gemm_half<1><<<GRID_G, 256, SMEM_B>>>(Wr[l], nullptr, dr[l + 1], p_agg, nullptr);
        else
            gemm_half<2><<<GRID_G, 256, SMEM_B>>>(Wr[2], nullptr, nullptr, p_agg, out);
    }
}

// round 8
// speedup vs baseline: 2.3439x; 1.4897x over previous
#include <cuda_runtime.h>
#include <cstdint>

#define NN 50000
#define CE 800000
#define C  128
#define NT 64
#define NTILES 782               // ceil(50000/64)
#define GRID_G 304               // 2 CTAs per SM * 152 SMs
#define S 132                    // smem row stride (floats), 132%32=4
#define SW_FL (128*S)            // 16896 floats
#define SX_FL (NT*S)             // 8448 floats
#define SMEM_B ((SW_FL+SX_FL)*4) // 101376 bytes -> 2 CTAs/SM
#define SCAN_BLOCKS 196          // 196*256 = 50176 >= NN

// scratch (allocation-free rule: __device__ globals)
__device__ __align__(16) float g_h[(size_t)NN * C];
__device__ __align__(16) float g_agg[(size_t)NN * C];
__device__ __align__(16) float g_y[(size_t)NN * C];

// CSR (rebuilt deterministically-enough every call; fp-order jitter only)
__device__ int g_deg[NN];
__device__ int g_row[NN];
__device__ int g_cur[NN];
__device__ int g_srcs[CE];
__device__ int g_bsum[256];
__device__ int g_boff[256];

// dtype flags resolved on-device
__device__ int g_ei_is64;
__device__ int g_mask_is4B;

// ---------------------------------------------------------------------------
__global__ void sniff_kernel(const void* ei, const void* m0) {
    if (blockIdx.x != 0 || threadIdx.x != 0) return;
    const long long* e64 = (const long long*)ei;
    int is64 = 1;
    for (int i = 0; i < 256; i++) {
        long long v = e64[i];
        if (v < 0 || v >= NN) { is64 = 0; break; }
    }
    g_ei_is64 = is64;
    const unsigned* mu = (const unsigned*)m0;
    int is4B = 1;
    for (int i = 0; i < 256; i++) {
        unsigned v = mu[i];
        if (v != 0u && v != 1u && v != 0x3F800000u) { is4B = 0; break; }
    }
    g_mask_is4B = is4B;
}

__device__ __forceinline__ uint4 load_mask4(const void* m, size_t idx4, int m4B) {
    if (m4B) { const uint4 v = ((const uint4*)m)[idx4]; return make_uint4(v.x, v.y, v.z, v.w); }
    const uchar4 v = ((const uchar4*)m)[idx4];
    return make_uint4(v.x, v.y, v.z, v.w);
}
__device__ __forceinline__ uint2 load_mask2(const void* m, size_t off, int m4B) {
    if (m4B) return *(const uint2*)((const unsigned*)m + off);
    const unsigned char* p = (const unsigned char*)m + off;
    return make_uint2(p[0], p[1]);
}
__device__ __forceinline__ float tf32r(float f) {
    uint32_t r;
    asm("cvt.rna.tf32.f32 %0, %1;" : "=r"(r) : "f"(f));
    return __uint_as_float(r);
}
__device__ __forceinline__ uint32_t tf32u(float f) {
    uint32_t r;
    asm("cvt.rna.tf32.f32 %0, %1;" : "=r"(r) : "f"(f));
    return r;
}
__device__ __forceinline__ void edge_sd(const void* ei, unsigned e, unsigned& s, unsigned& d) {
    if (g_ei_is64) {
        s = (unsigned)((const long long*)ei)[e];
        d = (unsigned)((const long long*)ei)[CE + e];
    } else {
        s = (unsigned)((const int*)ei)[e];
        d = (unsigned)((const int*)ei)[CE + e];
    }
}

// ---------------------------------------------------------------------------
// h = dropout(x) rounded to tf32
// ---------------------------------------------------------------------------
__global__ void init_kernel(const float* __restrict__ x, const void* __restrict__ d0) {
    const int m4B = g_mask_is4B;
    size_t i = (size_t)blockIdx.x * blockDim.x + threadIdx.x;
    if (i >= (size_t)NN * (C / 4)) return;
    float4 v = reinterpret_cast<const float4*>(x)[i];
    uint4 m = load_mask4(d0, i, m4B);
    float4 r;
    r.x = m.x ? tf32r(v.x * 2.5f) : 0.0f;
    r.y = m.y ? tf32r(v.y * 2.5f) : 0.0f;
    r.z = m.z ? tf32r(v.z * 2.5f) : 0.0f;
    r.w = m.w ? tf32r(v.w * 2.5f) : 0.0f;
    reinterpret_cast<float4*>(g_h)[i] = r;
}

// ---------------------------------------------------------------------------
// CSR build
// ---------------------------------------------------------------------------
__global__ void zero_deg_kernel() {
    int i = blockIdx.x * blockDim.x + threadIdx.x;
    if (i < NN) g_deg[i] = 0;
}
__global__ void hist_kernel(const void* __restrict__ ei) {
    unsigned e = blockIdx.x * blockDim.x + threadIdx.x;
    if (e >= CE) return;
    unsigned s, d;
    edge_sd(ei, e, s, d);
    if (s >= NN || d >= NN) return;
    atomicAdd(&g_deg[d], 1);
}
__global__ void scan_block_kernel() {
    __shared__ int sd[256];
    const int tx = threadIdx.x;
    int idx = blockIdx.x * 256 + tx;
    int d = (idx < NN) ? g_deg[idx] : 0;
    int val = d;
    sd[tx] = val;
    __syncthreads();
    #pragma unroll
    for (int off = 1; off < 256; off <<= 1) {
        int t = (tx >= off) ? sd[tx - off] : 0;
        __syncthreads();
        val += t;
        sd[tx] = val;
        __syncthreads();
    }
    if (idx < NN) g_row[idx] = val - d;          // exclusive within block
    if (tx == 255) g_bsum[blockIdx.x] = val;     // block total
}
__global__ void scan_tops_kernel() {
    __shared__ int sd[256];
    const int tx = threadIdx.x;
    int d = (tx < SCAN_BLOCKS) ? g_bsum[tx] : 0;
    int val = d;
    sd[tx] = val;
    __syncthreads();
    #pragma unroll
    for (int off = 1; off < 256; off <<= 1) {
        int t = (tx >= off) ? sd[tx - off] : 0;
        __syncthreads();
        val += t;
        sd[tx] = val;
        __syncthreads();
    }
    g_boff[tx] = val - d;                        // exclusive
}
__global__ void scan_fix_kernel() {
    int idx = blockIdx.x * 256 + threadIdx.x;
    if (idx >= NN) return;
    int r = g_row[idx] + g_boff[blockIdx.x];
    g_row[idx] = r;
    g_cur[idx] = r;
}
__global__ void fill_kernel(const void* __restrict__ ei) {
    unsigned e = blockIdx.x * blockDim.x + threadIdx.x;
    if (e >= CE) return;
    unsigned s, d;
    edge_sd(ei, e, s, d);
    if (s >= NN || d >= NN) return;
    int p = atomicAdd(&g_cur[d], 1);
    g_srcs[p] = (int)s;
}

// ---------------------------------------------------------------------------
// Gather-reduce: agg[n] = sum_{j in N(n)} h[j]. Warp per node, lane = float4
// of the row, 4 independent accumulators for MLP. No atomics, full overwrite.
// ---------------------------------------------------------------------------
__global__ void __launch_bounds__(256)
gather_kernel() {
    unsigned w = (blockIdx.x * blockDim.x + threadIdx.x) >> 5;
    if (w >= NN) return;
    const int lane = threadIdx.x & 31;
    const int start = g_row[w];
    const int deg = g_deg[w];
    float4 a0 = make_float4(0.f, 0.f, 0.f, 0.f), a1 = a0, a2 = a0, a3 = a0;
    int j = 0;
    for (; j + 4 <= deg; j += 4) {
        int s0 = g_srcs[start + j + 0];
        int s1 = g_srcs[start + j + 1];
        int s2 = g_srcs[start + j + 2];
        int s3 = g_srcs[start + j + 3];
        float4 v0 = reinterpret_cast<const float4*>(g_h + (size_t)s0 * C)[lane];
        float4 v1 = reinterpret_cast<const float4*>(g_h + (size_t)s1 * C)[lane];
        float4 v2 = reinterpret_cast<const float4*>(g_h + (size_t)s2 * C)[lane];
        float4 v3 = reinterpret_cast<const float4*>(g_h + (size_t)s3 * C)[lane];
        a0.x += v0.x; a0.y += v0.y; a0.z += v0.z; a0.w += v0.w;
        a1.x += v1.x; a1.y += v1.y; a1.z += v1.z; a1.w += v1.w;
        a2.x += v2.x; a2.y += v2.y; a2.z += v2.z; a2.w += v2.w;
        a3.x += v3.x; a3.y += v3.y; a3.z += v3.z; a3.w += v3.w;
    }
    for (; j < deg; j++) {
        int s0 = g_srcs[start + j];
        float4 v0 = reinterpret_cast<const float4*>(g_h + (size_t)s0 * C)[lane];
        a0.x += v0.x; a0.y += v0.y; a0.z += v0.z; a0.w += v0.w;
    }
    float4 r;
    r.x = (a0.x + a1.x) + (a2.x + a3.x);
    r.y = (a0.y + a1.y) + (a2.y + a3.y);
    r.z = (a0.z + a1.z) + (a2.z + a3.z);
    r.w = (a0.w + a1.w) + (a2.w + a3.w);
    reinterpret_cast<float4*>(g_agg + (size_t)w * C)[lane] = r;
}

// ---------------------------------------------------------------------------
// Half-K GEMM (K=128), tf32 mma.sync, persistent, cp.async-pipelined.
// MODE 0 (root):    g_y  = X(h)·W^T + bias
// MODE 1 (combine): g_h  = tf32(drop(relu(X(agg)·W^T + Y)))
// MODE 2 (final):   out  = X(agg)·W^T + Y
// ---------------------------------------------------------------------------
template <int MODE>
__global__ void __launch_bounds__(256, 2)
gemm_half(const float* __restrict__ W, const float* __restrict__ bias,
          const void* __restrict__ drop, const float* __restrict__ Xsrc,
          float* __restrict__ outp) {
    extern __shared__ float sm[];
    float* sW = sm;
    float* sX = sm + SW_FL;

    const int tid = threadIdx.x;
    const int m4B = g_mask_is4B;

    #pragma unroll 4
    for (int j = tid; j < 128 * 32; j += 256) {
        int o = j >> 5, kq = j & 31;
        float4 v = ((const float4*)W)[j];
        float4 t = make_float4(tf32r(v.x), tf32r(v.y), tf32r(v.z), tf32r(v.w));
        *(float4*)(sW + o * S + kq * 4) = t;
    }

    uint32_t sXaddr;
    asm("{.reg .u64 t; cvta.to.shared.u64 t, %1; cvt.u32.u64 %0, t;}"
        : "=r"(sXaddr) : "l"(sX));

    const int wid = tid >> 5, lane = tid & 31;
    const int warpM = wid & 1, warpN = wid >> 1;
    const int lr = lane >> 2, lc = lane & 3;

    float2 bias2[4];
    if (MODE == 0) {
        #pragma unroll
        for (int nf = 0; nf < 4; nf++)
            bias2[nf] = *(const float2*)(bias + warpN * 32 + nf * 8 + lc * 2);
    }

    int tile = blockIdx.x;
    {
        #pragma unroll
        for (int j = 0; j < 8; j++) {
            int idx = tid + j * 256;
            int row = idx & 63, ch = idx >> 6;
            int node = tile * NT + row;
            const float* src = Xsrc + (size_t)(node < NN ? node : 0) * C + ch * 4;
            int sz = (node < NN) ? 16 : 0;
            asm volatile("cp.async.cg.shared.global [%0], [%1], 16, %2;"
                         :: "r"(sXaddr + (unsigned)(row * S + ch * 4) * 4), "l"(src), "r"(sz));
        }
        asm volatile("cp.async.commit_group;" ::: "memory");
    }

    for (; tile < NTILES; tile += GRID_G) {
        asm volatile("cp.async.wait_group 0;" ::: "memory");
        __syncthreads();

        float d[2][4][4];
        #pragma unroll
        for (int mf = 0; mf < 2; mf++)
            #pragma unroll
            for (int nf = 0; nf < 4; nf++)
                #pragma unroll
                for (int j = 0; j < 4; j++) d[mf][nf][j] = 0.0f;

        #pragma unroll 8
        for (int ks = 0; ks < 16; ks++) {
            const int kb = ks * 8;
            uint32_t a[2][4], bb[4][2];
            #pragma unroll
            for (int mf = 0; mf < 2; mf++) {
                const float* p = sX + (warpM * 32 + mf * 16 + lr) * S + kb + lc;
                a[mf][0] = tf32u(p[0]);
                a[mf][2] = tf32u(p[4]);
                a[mf][1] = tf32u(p[8 * S]);
                a[mf][3] = tf32u(p[8 * S + 4]);
            }
            #pragma unroll
            for (int nf = 0; nf < 4; nf++) {
                const float* p = sW + (warpN * 32 + nf * 8 + lr) * S + kb + lc;
                bb[nf][0] = __float_as_uint(p[0]);
                bb[nf][1] = __float_as_uint(p[4]);
            }
            #pragma unroll
            for (int mf = 0; mf < 2; mf++)
                #pragma unroll
                for (int nf = 0; nf < 4; nf++) {
                    asm volatile(
                        "mma.sync.aligned.m16n8k8.row.col.f32.tf32.tf32.f32 "
                        "{%0,%1,%2,%3}, {%4,%5,%6,%7}, {%8,%9}, {%0,%1,%2,%3};"
                        : "+f"(d[mf][nf][0]), "+f"(d[mf][nf][1]),
                          "+f"(d[mf][nf][2]), "+f"(d[mf][nf][3])
                        : "r"(a[mf][0]), "r"(a[mf][1]), "r"(a[mf][2]), "r"(a[mf][3]),
                          "r"(bb[nf][0]), "r"(bb[nf][1]));
                }
        }
        __syncthreads();

        int nxt = tile + GRID_G;
        if (nxt < NTILES) {
            #pragma unroll
            for (int j = 0; j < 8; j++) {
                int idx = tid + j * 256;
                int row = idx & 63, ch = idx >> 6;
                int node = nxt * NT + row;
                const float* src = Xsrc + (size_t)(node < NN ? node : 0) * C + ch * 4;
                int sz = (node < NN) ? 16 : 0;
                asm volatile("cp.async.cg.shared.global [%0], [%1], 16, %2;"
                             :: "r"(sXaddr + (unsigned)(row * S + ch * 4) * 4), "l"(src), "r"(sz));
            }
        }
        asm volatile("cp.async.commit_group;" ::: "memory");

        #pragma unroll
        for (int mf = 0; mf < 2; mf++) {
            #pragma unroll
            for (int rr = 0; rr < 2; rr++) {
                int node = tile * NT + warpM * 32 + mf * 16 + rr * 8 + lr;
                if (node >= NN) continue;
                #pragma unroll
                for (int nf = 0; nf < 4; nf++) {
                    int o = warpN * 32 + nf * 8 + lc * 2;
                    float vx = d[mf][nf][rr * 2 + 0];
                    float vy = d[mf][nf][rr * 2 + 1];
                    size_t off = (size_t)node * C + o;
                    if (MODE == 0) {
                        vx += bias2[nf].x; vy += bias2[nf].y;
                        *(float2*)(g_y + off) = make_float2(vx, vy);
                    } else {
                        float2 y = *(const float2*)(g_y + off);
                        vx += y.x; vy += y.y;
                        if (MODE == 1) {
                            vx = fmaxf(vx, 0.0f);
                            vy = fmaxf(vy, 0.0f);
                            uint2 m = load_mask2(drop, off, m4B);
                            vx = m.x ? tf32r(vx * 2.5f) : 0.0f;
                            vy = m.y ? tf32r(vy * 2.5f) : 0.0f;
                            *(float2*)(g_h + off) = make_float2(vx, vy);
                        } else {
                            *(float2*)(outp + off) = make_float2(vx, vy);
                        }
                    }
                }
            }
        }
    }
}

// ---------------------------------------------------------------------------
extern "C" void kernel_launch(void* const* d_in, const int* in_sizes, int n_in,
                              void* d_out, int out_size) {
    const float* x   = (const float*)d_in[0];
    const void*  ei  = d_in[1];
    const float* Wr[3] = {(const float*)d_in[2], (const float*)d_in[5], (const float*)d_in[8]};
    const float* Wo[3] = {(const float*)d_in[3], (const float*)d_in[6], (const float*)d_in[9]};
    const float* bv[3] = {(const float*)d_in[4], (const float*)d_in[7], (const float*)d_in[10]};
    const void*  dr[3] = {d_in[11], d_in[12], d_in[13]};
    float* out = (float*)d_out;

    static cudaStream_t s2 = nullptr;
    static cudaEvent_t evF = nullptr, evJ = nullptr;
    static float *p_h = nullptr, *p_agg = nullptr;
    if (!s2) {
        cudaStreamCreateWithFlags(&s2, cudaStreamNonBlocking);
        cudaEventCreateWithFlags(&evF, cudaEventDisableTiming);
        cudaEventCreateWithFlags(&evJ, cudaEventDisableTiming);
        cudaGetSymbolAddress((void**)&p_h, g_h);
        cudaGetSymbolAddress((void**)&p_agg, g_agg);
        cudaFuncSetAttribute(gemm_half<0>, cudaFuncAttributeMaxDynamicSharedMemorySize, SMEM_B);
        cudaFuncSetAttribute(gemm_half<1>, cudaFuncAttributeMaxDynamicSharedMemorySize, SMEM_B);
        cudaFuncSetAttribute(gemm_half<2>, cudaFuncAttributeMaxDynamicSharedMemorySize, SMEM_B);
    }

    const int initBlocks = (NN * (C / 4) + 255) / 256;
    const int edgeBlocks = (CE + 255) / 256;
    const int nodeBlocks = (NN + 255) / 256;
    const int gathBlocks = (NN * 32 + 255) / 256;    // warp per node

    sniff_kernel<<<1, 32>>>(ei, dr[0]);
    init_kernel<<<initBlocks, 256>>>(x, dr[0]);

    // CSR build (once per call)
    zero_deg_kernel<<<nodeBlocks, 256>>>();
    hist_kernel<<<edgeBlocks, 256>>>(ei);
    scan_block_kernel<<<SCAN_BLOCKS, 256>>>();
    scan_tops_kernel<<<1, 256>>>();
    scan_fix_kernel<<<SCAN_BLOCKS, 256>>>();
    fill_kernel<<<edgeBlocks, 256>>>(ei);

    for (int l = 0; l < 3; l++) {
        // fork: root pass (Y = h*Wroot^T + b) runs concurrently with gather
        cudaEventRecord(evF, 0);
        cudaStreamWaitEvent(s2, evF, 0);
        gemm_half<0><<<GRID_G, 256, SMEM_B, s2>>>(Wo[l], bv[l], nullptr, p_h, nullptr);
        cudaEventRecord(evJ, s2);

        gather_kernel<<<gathBlocks, 256>>>();

        cudaStreamWaitEvent(0, evJ, 0);
        if (l < 2)
            gemm_half<1><<<GRID_G, 256, SMEM_B>>>(Wr[l], nullptr, dr[l + 1], p_agg, nullptr);
        else
            gemm_half<2><<<GRID_G, 256, SMEM_B>>>(Wr[2], nullptr, nullptr, p_agg, out);
    }
}